// round 1
// baseline (speedup 1.0000x reference)
#include <cuda_runtime.h>
#include <math.h>

#define BATCH_  256
#define T_      1024
#define IDIM_   128
#define H_      256
#define G_      1024   // 4*H

// Scratch (static __device__ globals: allocation-free per harness rules)
__device__ float        g_xp[(size_t)T_ * BATCH_ * G_];  // [t][b][4H]  1 GiB
__device__ float        g_h[2][BATCH_ * H_];             // double-buffered h
__device__ unsigned int g_counter;

// ---------------------------------------------------------------------------
// init: zero h buffer 0 and barrier counter
// ---------------------------------------------------------------------------
__global__ void init_kernel() {
    int i = blockIdx.x * blockDim.x + threadIdx.x;
    if (i < BATCH_ * H_) g_h[0][i] = 0.0f;
    if (i == 0) g_counter = 0u;
}

// ---------------------------------------------------------------------------
// x-projection GEMM: g_xp[t][b][g] = sum_k x[b][t][k]*W_ih[k][g] + b_ih[g]+b_hh[g]
// Tile 128 rows (flattened b*T+t) x 64 cols, K=128 resident in SMEM.
// 128 threads, 8x8 microkernel.
// ---------------------------------------------------------------------------
__global__ void __launch_bounds__(128) xproj_kernel(
    const float* __restrict__ x, const float* __restrict__ Wih,
    const float* __restrict__ bih, const float* __restrict__ bhh)
{
    extern __shared__ float sm[];
    float* Xs = sm;             // [128][128] row-major (row, k)
    float* Ws = sm + 128 * 128; // [128][64]  (k, n)
    const int rowBase = blockIdx.x * 128;
    const int colBase = blockIdx.y * 64;
    const int tid = threadIdx.x;

    // load X tile (coalesced, no transpose needed)
    for (int idx = tid; idx < 4096; idx += 128) {
        int r = idx >> 5, k4 = (idx & 31) << 2;
        *reinterpret_cast<float4*>(Xs + r * 128 + k4) =
            *reinterpret_cast<const float4*>(x + (size_t)(rowBase + r) * IDIM_ + k4);
    }
    // load W tile
    for (int idx = tid; idx < 2048; idx += 128) {
        int k = idx >> 4, n4 = (idx & 15) << 2;
        *reinterpret_cast<float4*>(Ws + k * 64 + n4) =
            *reinterpret_cast<const float4*>(Wih + (size_t)k * G_ + colBase + n4);
    }
    __syncthreads();

    const int tx = tid & 7;   // col group (8 cols each)
    const int ty = tid >> 3;  // row group (8 rows each)
    float acc[8][8];
#pragma unroll
    for (int i = 0; i < 8; i++)
#pragma unroll
        for (int j = 0; j < 8; j++) acc[i][j] = 0.0f;

    const float* xr = Xs + (ty * 8) * 128;
    const float* wc = Ws + tx * 8;
#pragma unroll 4
    for (int k = 0; k < 128; k++) {
        float4 wa = *reinterpret_cast<const float4*>(wc + k * 64);
        float4 wb = *reinterpret_cast<const float4*>(wc + k * 64 + 4);
        float wv[8] = {wa.x, wa.y, wa.z, wa.w, wb.x, wb.y, wb.z, wb.w};
#pragma unroll
        for (int i = 0; i < 8; i++) {
            float xv = xr[i * 128 + k];
#pragma unroll
            for (int j = 0; j < 8; j++) acc[i][j] += xv * wv[j];
        }
    }

    float bias[8];
#pragma unroll
    for (int j = 0; j < 8; j++) {
        int col = colBase + tx * 8 + j;
        bias[j] = bih[col] + bhh[col];
    }
#pragma unroll
    for (int i = 0; i < 8; i++) {
        int R = rowBase + ty * 8 + i;
        int b = R >> 10;          // R / T_
        int t = R & (T_ - 1);     // R % T_
        float* dst = g_xp + ((size_t)t * BATCH_ + b) * G_ + colBase + tx * 8;
        float4 o0 = make_float4(acc[i][0] + bias[0], acc[i][1] + bias[1],
                                acc[i][2] + bias[2], acc[i][3] + bias[3]);
        float4 o1 = make_float4(acc[i][4] + bias[4], acc[i][5] + bias[5],
                                acc[i][6] + bias[6], acc[i][7] + bias[7]);
        *reinterpret_cast<float4*>(dst)     = o0;
        *reinterpret_cast<float4*>(dst + 4) = o1;
    }
}

// ---------------------------------------------------------------------------
// Persistent LSTM recurrence. 128 CTAs (16 batch-tiles x 8 col-tiles), 256 thr.
// Each CTA: W_hh slice [256 K][128 gate cols] resident in SMEM for all steps.
// Per step: GEMM (8-warp K-split, 8x8 microkernel) -> reduce -> gates -> h/c.
// Grid barrier via atomic counter (all 128 CTAs resident: 215KB smem => 1/SM).
// ---------------------------------------------------------------------------
__global__ void __launch_bounds__(256, 1) lstm_kernel(const float* __restrict__ Whh)
{
    extern __shared__ float sm[];
    float* Ws   = sm;                    // [256][128]   32768 f
    float* hs   = Ws + 256 * 128;        // [16][256]     4096 f
    float* part = hs + 16 * 256;         // [8][16][128] 16384 f
    float* cs   = part + 8 * 2048;       // [16][32]       512 f
    // total 53760 floats = 215040 bytes

    const int tid = threadIdx.x;
    const int mt = blockIdx.x & 15;      // batch tile
    const int ct = blockIdx.x >> 4;      // h-column tile (0..7)
    const int m0 = mt * 16;
    const int c0 = ct * 32;

    // load W_hh slice: local col lc -> global col (lc/32)*256 + c0 + lc%32
    for (int idx = tid; idx < 256 * 128; idx += 256) {
        int k = idx >> 7, lc = idx & 127;
        Ws[idx] = Whh[(size_t)k * G_ + ((lc >> 5) << 8) + c0 + (lc & 31)];
    }
    if (tid < 512) cs[tid] = 0.0f;

    const int warp = tid >> 5;           // k-group (0..7), k range [warp*32, +32)
    const int lane = tid & 31;
    const int rb = lane >> 4;            // row block (0..1) -> rows rb*8..+8
    const int cb = lane & 15;            // col block (0..15) -> cols cb*8..+8
    const int k0 = warp * 32;

    __syncthreads();

    for (int t = 0; t < T_; t++) {
        // --- load h tile (previous state) with L1-bypassing loads ---
        const float* hb = &g_h[t & 1][0];
        for (int idx = tid; idx < 1024; idx += 256) {
            int r = idx >> 6, k4 = (idx & 63) << 2;
            float4 v = __ldcg(reinterpret_cast<const float4*>(hb + (m0 + r) * H_ + k4));
            *reinterpret_cast<float4*>(hs + r * 256 + k4) = v;
        }
        __syncthreads();

        // --- GEMM: gates_partial[16x128] over this warp's K-slice ---
        float acc[8][8];
#pragma unroll
        for (int i = 0; i < 8; i++)
#pragma unroll
            for (int j = 0; j < 8; j++) acc[i][j] = 0.0f;

        const float* wp = Ws + k0 * 128 + cb * 8;
        const float* hp = hs + (rb * 8) * 256 + k0;
#pragma unroll 8
        for (int kk = 0; kk < 32; kk++) {
            float4 wa = *reinterpret_cast<const float4*>(wp + kk * 128);
            float4 wb2 = *reinterpret_cast<const float4*>(wp + kk * 128 + 4);
            float wv[8] = {wa.x, wa.y, wa.z, wa.w, wb2.x, wb2.y, wb2.z, wb2.w};
#pragma unroll
            for (int i = 0; i < 8; i++) {
                float hv = hp[i * 256 + kk];
#pragma unroll
                for (int j = 0; j < 8; j++) acc[i][j] += hv * wv[j];
            }
        }

        // --- store partials ---
        float* pp = part + warp * 2048 + (rb * 8) * 128 + cb * 8;
#pragma unroll
        for (int i = 0; i < 8; i++) {
            *reinterpret_cast<float4*>(pp + i * 128) =
                make_float4(acc[i][0], acc[i][1], acc[i][2], acc[i][3]);
            *reinterpret_cast<float4*>(pp + i * 128 + 4) =
                make_float4(acc[i][4], acc[i][5], acc[i][6], acc[i][7]);
        }
        __syncthreads();

        // --- reduce K-split, add x_proj, gate activations, update c/h ---
        float* hw = &g_h[(t + 1) & 1][0];
        for (int e = tid; e < 512; e += 256) {
            int r = e >> 5, j = e & 31;
            float gi = 0.f, gf = 0.f, gg = 0.f, go = 0.f;
#pragma unroll
            for (int g8 = 0; g8 < 8; g8++) {
                const float* p = part + g8 * 2048 + r * 128;
                gi += p[j];
                gf += p[32 + j];
                gg += p[64 + j];
                go += p[96 + j];
            }
            size_t xb = ((size_t)t * BATCH_ + m0 + r) * G_ + c0 + j;
            gi += g_xp[xb];
            gf += g_xp[xb + 256];
            gg += g_xp[xb + 512];
            go += g_xp[xb + 768];

            float it = 1.0f / (1.0f + __expf(-gi));
            float ft = 1.0f / (1.0f + __expf(-gf));
            float gt = tanhf(gg);
            float ot = 1.0f / (1.0f + __expf(-go));
            float c  = ft * cs[e] + it * gt;
            cs[e] = c;
            float h = ot * tanhf(c);
            __stcg(hw + (m0 + r) * H_ + c0 + j, h);
        }

        // --- grid barrier ---
        __threadfence();
        __syncthreads();
        if (tid == 0) {
            atomicAdd(&g_counter, 1u);
            unsigned tgt = (unsigned)(t + 1) * (unsigned)gridDim.x;
            while (*(volatile unsigned int*)&g_counter < tgt) { }
            __threadfence();
        }
        __syncthreads();
    }
}

// ---------------------------------------------------------------------------
// out[b][o] = sum_k h_T[b][k] * W_out[k][o] + b_out[o]
// ---------------------------------------------------------------------------
__global__ void __launch_bounds__(128) out_kernel(
    const float* __restrict__ Wout, const float* __restrict__ bout,
    float* __restrict__ out)
{
    __shared__ float hrow[256];
    const int b = blockIdx.x;
    const int o = threadIdx.x;
    const float* h = &g_h[0][b * H_];   // T even -> final h in buffer 0
    hrow[o]       = h[o];
    hrow[o + 128] = h[o + 128];
    __syncthreads();
    float acc = bout[o];
#pragma unroll 8
    for (int k = 0; k < 256; k++) acc += hrow[k] * Wout[k * 128 + o];
    out[b * 128 + o] = acc;
}

// ---------------------------------------------------------------------------
extern "C" void kernel_launch(void* const* d_in, const int* in_sizes, int n_in,
                              void* d_out, int out_size)
{
    const float* x    = (const float*)d_in[0];  // [256,1024,128]
    const float* Wih  = (const float*)d_in[1];  // [128,1024]
    const float* Whh  = (const float*)d_in[2];  // [256,1024]
    const float* bih  = (const float*)d_in[3];  // [1024]
    const float* bhh  = (const float*)d_in[4];  // [1024]
    const float* Wout = (const float*)d_in[5];  // [256,128]
    const float* bout = (const float*)d_in[6];  // [128]
    float* out = (float*)d_out;                 // [256,128]

    cudaFuncSetAttribute(xproj_kernel, cudaFuncAttributeMaxDynamicSharedMemorySize,
                         98304);
    cudaFuncSetAttribute(lstm_kernel, cudaFuncAttributeMaxDynamicSharedMemorySize,
                         215040);

    init_kernel<<<(BATCH_ * H_ + 255) / 256, 256>>>();
    xproj_kernel<<<dim3((BATCH_ * T_) / 128, G_ / 64), 128, 98304>>>(x, Wih, bih, bhh);
    lstm_kernel<<<128, 256, 215040>>>(Whh);
    out_kernel<<<BATCH_, 128>>>(Wout, bout, out);
}

// round 5
// speedup vs baseline: 1.0624x; 1.0624x over previous
#include <cuda_runtime.h>
#include <math.h>

typedef unsigned long long u64;

#define BATCH_  256
#define T_      1024
#define IDIM_   128
#define H_      256
#define G_      1024   // 4*H

// Scratch (static __device__ globals: allocation-free per harness rules)
__device__ float        g_xp[(size_t)T_ * BATCH_ * G_];  // [t][b][4H]
__device__ float        g_h[2][BATCH_ * H_];             // double-buffered h
__device__ unsigned int g_counter;

// ---------------------------------------------------------------------------
// packed f32x2 helpers
// ---------------------------------------------------------------------------
__device__ __forceinline__ void fma2(u64& d, u64 a, u64 b) {
    // d.lo += a.lo*b.lo ; d.hi += a.hi*b.hi
    asm("fma.rn.f32x2 %0, %1, %2, %0;" : "+l"(d) : "l"(a), "l"(b));
}
__device__ __forceinline__ u64 splat2(float x) {
    u64 r;
    asm("mov.b64 %0, {%1, %1};" : "=l"(r) : "f"(x));
    return r;
}
__device__ __forceinline__ float2 u2f2(u64 v) {
    return *reinterpret_cast<float2*>(&v);
}

// ---------------------------------------------------------------------------
// init: zero h buffer 0 and barrier counter
// ---------------------------------------------------------------------------
__global__ void init_kernel() {
    int i = blockIdx.x * blockDim.x + threadIdx.x;
    if (i < BATCH_ * H_) g_h[0][i] = 0.0f;
    if (i == 0) g_counter = 0u;
}

// ---------------------------------------------------------------------------
// x-projection GEMM: g_xp[t][b][g] = sum_k x[b][t][k]*W_ih[k][g] + b_ih[g]+b_hh[g]
// Tile 128 rows (flattened b*T+t) x 64 cols, K=128 resident in SMEM.
// 128 threads, 8x8 microkernel, column-paired f32x2 accumulators.
// Layouts identical to the known-good R1 kernel.
// ---------------------------------------------------------------------------
__global__ void __launch_bounds__(128) xproj_kernel(
    const float* __restrict__ x, const float* __restrict__ Wih,
    const float* __restrict__ bih, const float* __restrict__ bhh)
{
    extern __shared__ float sm[];
    float* Xs = sm;             // [128][128] row-major (row, k)
    float* Ws = sm + 128 * 128; // [128][64]  (k, n)
    const int rowBase = blockIdx.x * 128;
    const int colBase = blockIdx.y * 64;
    const int tid = threadIdx.x;

    // load X tile (coalesced, no transpose needed)
    for (int idx = tid; idx < 4096; idx += 128) {
        int r = idx >> 5, k4 = (idx & 31) << 2;
        *reinterpret_cast<float4*>(Xs + r * 128 + k4) =
            *reinterpret_cast<const float4*>(x + (size_t)(rowBase + r) * IDIM_ + k4);
    }
    // load W tile
    for (int idx = tid; idx < 2048; idx += 128) {
        int k = idx >> 4, n4 = (idx & 15) << 2;
        *reinterpret_cast<float4*>(Ws + k * 64 + n4) =
            *reinterpret_cast<const float4*>(Wih + (size_t)k * G_ + colBase + n4);
    }
    __syncthreads();

    const int tx = tid & 7;   // col group (8 cols each)
    const int ty = tid >> 3;  // row group (8 rows each)
    u64 acc2[8][4];           // [row][col-pair]; .lo = col 2c, .hi = col 2c+1
#pragma unroll
    for (int i = 0; i < 8; i++)
#pragma unroll
        for (int j = 0; j < 4; j++) acc2[i][j] = 0ull;

    const float* xr = Xs + (ty * 8) * 128;
    const float* wc = Ws + tx * 8;
#pragma unroll 4
    for (int k = 0; k < 128; k++) {
        const float* wrow = wc + k * 64;
        u64 w0 = *reinterpret_cast<const u64*>(wrow);
        u64 w1 = *reinterpret_cast<const u64*>(wrow + 2);
        u64 w2 = *reinterpret_cast<const u64*>(wrow + 4);
        u64 w3 = *reinterpret_cast<const u64*>(wrow + 6);
#pragma unroll
        for (int i = 0; i < 8; i++) {
            u64 xv = splat2(xr[i * 128 + k]);
            fma2(acc2[i][0], xv, w0);
            fma2(acc2[i][1], xv, w1);
            fma2(acc2[i][2], xv, w2);
            fma2(acc2[i][3], xv, w3);
        }
    }

    float bias[8];
#pragma unroll
    for (int j = 0; j < 8; j++) {
        int col = colBase + tx * 8 + j;
        bias[j] = bih[col] + bhh[col];
    }
#pragma unroll
    for (int i = 0; i < 8; i++) {
        int R = rowBase + ty * 8 + i;
        int b = R >> 10;          // R / T_
        int t = R & (T_ - 1);     // R % T_
        float* dst = g_xp + ((size_t)t * BATCH_ + b) * G_ + colBase + tx * 8;
        float2 a0 = u2f2(acc2[i][0]), a1 = u2f2(acc2[i][1]);
        float2 a2 = u2f2(acc2[i][2]), a3 = u2f2(acc2[i][3]);
        float4 o0 = make_float4(a0.x + bias[0], a0.y + bias[1],
                                a1.x + bias[2], a1.y + bias[3]);
        float4 o1 = make_float4(a2.x + bias[4], a2.y + bias[5],
                                a3.x + bias[6], a3.y + bias[7]);
        *reinterpret_cast<float4*>(dst)     = o0;
        *reinterpret_cast<float4*>(dst + 4) = o1;
    }
}

// ---------------------------------------------------------------------------
// Persistent LSTM recurrence. 128 CTAs (16 batch-tiles x 8 col-tiles), 256 thr.
// Each CTA: W_hh slice [256 K][128 gate cols] resident in SMEM for all steps.
// Per step: GEMM (8-warp K-split, 8x8 microkernel, f32x2 col-pairs) -> reduce
// -> gates -> h/c. Global grid barrier via atomic counter (known-good R1 form).
// ---------------------------------------------------------------------------
__global__ void __launch_bounds__(256, 1) lstm_kernel(const float* __restrict__ Whh)
{
    extern __shared__ float sm[];
    float* Ws   = sm;                    // [256][128]   32768 f
    float* hs   = Ws + 256 * 128;        // [16][256]     4096 f
    float* part = hs + 16 * 256;         // [8][16][128] 16384 f
    float* cs   = part + 8 * 2048;       // [16][32]       512 f
    // total 53760 floats = 215040 bytes

    const int tid = threadIdx.x;
    const int mt = blockIdx.x & 15;      // batch tile
    const int ct = blockIdx.x >> 4;      // h-column tile (0..7)
    const int m0 = mt * 16;
    const int c0 = ct * 32;

    // load W_hh slice: local col lc -> global col (lc/32)*256 + c0 + lc%32
    for (int idx = tid; idx < 256 * 128; idx += 256) {
        int k = idx >> 7, lc = idx & 127;
        Ws[idx] = Whh[(size_t)k * G_ + ((lc >> 5) << 8) + c0 + (lc & 31)];
    }
    if (tid < 512) cs[tid] = 0.0f;

    const int warp = tid >> 5;           // k-group (0..7), k range [warp*32, +32)
    const int lane = tid & 31;
    const int rb = lane >> 4;            // row block (0..1) -> rows rb*8..+8
    const int cb = lane & 15;            // col block (0..15) -> cols cb*8..+8
    const int k0 = warp * 32;

    __syncthreads();

    for (int t = 0; t < T_; t++) {
        // --- load h tile (previous state) with L1-bypassing loads ---
        const float* hb = &g_h[t & 1][0];
        for (int idx = tid; idx < 1024; idx += 256) {
            int r = idx >> 6, k4 = (idx & 63) << 2;
            float4 v = __ldcg(reinterpret_cast<const float4*>(hb + (m0 + r) * H_ + k4));
            *reinterpret_cast<float4*>(hs + r * 256 + k4) = v;
        }
        __syncthreads();

        // --- GEMM: gates_partial[16x128] over this warp's K-slice ---
        u64 acc2[8][4];                  // [row][col-pair]
#pragma unroll
        for (int i = 0; i < 8; i++)
#pragma unroll
            for (int j = 0; j < 4; j++) acc2[i][j] = 0ull;

        const float* wp = Ws + k0 * 128 + cb * 8;
        const float* hp = hs + (rb * 8) * 256 + k0;
#pragma unroll 8
        for (int kk = 0; kk < 32; kk++) {
            const float* wrow = wp + kk * 128;
            u64 w0 = *reinterpret_cast<const u64*>(wrow);
            u64 w1 = *reinterpret_cast<const u64*>(wrow + 2);
            u64 w2 = *reinterpret_cast<const u64*>(wrow + 4);
            u64 w3 = *reinterpret_cast<const u64*>(wrow + 6);
#pragma unroll
            for (int i = 0; i < 8; i++) {
                u64 hv = splat2(hp[i * 256 + kk]);
                fma2(acc2[i][0], hv, w0);
                fma2(acc2[i][1], hv, w1);
                fma2(acc2[i][2], hv, w2);
                fma2(acc2[i][3], hv, w3);
            }
        }

        // --- store partials ---
        float* pp = part + warp * 2048 + (rb * 8) * 128 + cb * 8;
#pragma unroll
        for (int i = 0; i < 8; i++) {
            float2 a0 = u2f2(acc2[i][0]), a1 = u2f2(acc2[i][1]);
            float2 a2 = u2f2(acc2[i][2]), a3 = u2f2(acc2[i][3]);
            *reinterpret_cast<float4*>(pp + i * 128) =
                make_float4(a0.x, a0.y, a1.x, a1.y);
            *reinterpret_cast<float4*>(pp + i * 128 + 4) =
                make_float4(a2.x, a2.y, a3.x, a3.y);
        }
        __syncthreads();

        // --- reduce K-split, add x_proj, gate activations, update c/h ---
        float* hw = &g_h[(t + 1) & 1][0];
        for (int e = tid; e < 512; e += 256) {
            int r = e >> 5, j = e & 31;
            float gi = 0.f, gf = 0.f, gg = 0.f, go = 0.f;
#pragma unroll
            for (int g8 = 0; g8 < 8; g8++) {
                const float* p = part + g8 * 2048 + r * 128;
                gi += p[j];
                gf += p[32 + j];
                gg += p[64 + j];
                go += p[96 + j];
            }
            size_t xb = ((size_t)t * BATCH_ + m0 + r) * G_ + c0 + j;
            gi += g_xp[xb];
            gf += g_xp[xb + 256];
            gg += g_xp[xb + 512];
            go += g_xp[xb + 768];

            float it = 1.0f / (1.0f + __expf(-gi));
            float ft = 1.0f / (1.0f + __expf(-gf));
            float gt = tanhf(gg);
            float ot = 1.0f / (1.0f + __expf(-go));
            float c  = ft * cs[e] + it * gt;
            cs[e] = c;
            float h = ot * tanhf(c);
            __stcg(hw + (m0 + r) * H_ + c0 + j, h);
        }

        // --- grid barrier ---
        __threadfence();
        __syncthreads();
        if (tid == 0) {
            atomicAdd(&g_counter, 1u);
            unsigned tgt = (unsigned)(t + 1) * (unsigned)gridDim.x;
            while (*(volatile unsigned int*)&g_counter < tgt) { }
            __threadfence();
        }
        __syncthreads();
    }
}

// ---------------------------------------------------------------------------
// out[b][o] = sum_k h_T[b][k] * W_out[k][o] + b_out[o]
// ---------------------------------------------------------------------------
__global__ void __launch_bounds__(128) out_kernel(
    const float* __restrict__ Wout, const float* __restrict__ bout,
    float* __restrict__ out)
{
    __shared__ float hrow[256];
    const int b = blockIdx.x;
    const int o = threadIdx.x;
    const float* h = &g_h[0][b * H_];   // T even -> final h in buffer 0
    hrow[o]       = h[o];
    hrow[o + 128] = h[o + 128];
    __syncthreads();
    float acc = bout[o];
#pragma unroll 8
    for (int k = 0; k < 256; k++) acc += hrow[k] * Wout[k * 128 + o];
    out[b * 128 + o] = acc;
}

// ---------------------------------------------------------------------------
extern "C" void kernel_launch(void* const* d_in, const int* in_sizes, int n_in,
                              void* d_out, int out_size)
{
    const float* x    = (const float*)d_in[0];  // [256,1024,128]
    const float* Wih  = (const float*)d_in[1];  // [128,1024]
    const float* Whh  = (const float*)d_in[2];  // [256,1024]
    const float* bih  = (const float*)d_in[3];  // [1024]
    const float* bhh  = (const float*)d_in[4];  // [1024]
    const float* Wout = (const float*)d_in[5];  // [256,128]
    const float* bout = (const float*)d_in[6];  // [128]
    float* out = (float*)d_out;                 // [256,128]

    cudaFuncSetAttribute(xproj_kernel, cudaFuncAttributeMaxDynamicSharedMemorySize,
                         98304);
    cudaFuncSetAttribute(lstm_kernel, cudaFuncAttributeMaxDynamicSharedMemorySize,
                         215040);

    init_kernel<<<(BATCH_ * H_ + 255) / 256, 256>>>();
    xproj_kernel<<<dim3((BATCH_ * T_) / 128, G_ / 64), 128, 98304>>>(x, Wih, bih, bhh);
    lstm_kernel<<<128, 256, 215040>>>(Whh);
    out_kernel<<<BATCH_, 128>>>(Wout, bout, out);
}